// round 1
// baseline (speedup 1.0000x reference)
#include <cuda_runtime.h>

// LightGCN propagation:
//   all_emb = concat(user_emb, item_emb)            (N = 300000, D = 64)
//   acc = all_emb
//   repeat 3x: emb = segment_sum(vals * emb[cols], rows); acc += emb
//   out = acc / 4
//
// Strategy: edge-parallel SpMM with vectorized fire-and-forget L2 reductions
// (red.global.add.v4.f32), 16 threads per edge (one float4 each). The 76.8 MB
// embedding table fits in L2, so gathers + atomics should be L2-resident.

#define DIM        64
#define DIM4       16           // float4s per row
#define N_TOTAL_MAX 300000
#define TPB        256

// Scratch ping-pong buffers (alloc-free rule: __device__ globals).
__device__ float g_bufA[(size_t)N_TOTAL_MAX * DIM];
__device__ float g_bufB[(size_t)N_TOTAL_MAX * DIM];

// --- init: bufA = concat(user,item); acc(d_out) = same; bufB = 0 -----------
__global__ void lg_init(const float4* __restrict__ user,
                        const float4* __restrict__ item,
                        float4* __restrict__ acc,
                        int n_user4, int n_total4) {
    int i = blockIdx.x * blockDim.x + threadIdx.x;
    if (i >= n_total4) return;
    float4 v = (i < n_user4) ? user[i] : item[i - n_user4];
    reinterpret_cast<float4*>(g_bufA)[i] = v;
    acc[i] = v;
    reinterpret_cast<float4*>(g_bufB)[i] = make_float4(0.f, 0.f, 0.f, 0.f);
}

// --- SpMM: out[rows[e]] += vals[e] * in[cols[e]], 16 threads per edge ------
__global__ void lg_spmm(const float* __restrict__ in,
                        float*       __restrict__ out,
                        const float* __restrict__ vals,
                        const int*   __restrict__ rows,
                        const int*   __restrict__ cols,
                        int nnz) {
    long long t = (long long)blockIdx.x * blockDim.x + threadIdx.x;
    int e = (int)(t >> 4);          // edge index
    int c = (int)(t & 15);          // float4 slot within row
    if (e >= nnz) return;

    int   row = __ldg(rows + e);
    int   col = __ldg(cols + e);
    float v   = __ldg(vals + e);

    float4 x = __ldg(reinterpret_cast<const float4*>(in + (long long)col * DIM) + c);
    x.x *= v; x.y *= v; x.z *= v; x.w *= v;

    float* dst = out + (long long)row * DIM + c * 4;
    asm volatile("red.global.add.v4.f32 [%0], {%1, %2, %3, %4};"
                 :: "l"(dst), "f"(x.x), "f"(x.y), "f"(x.z), "f"(x.w)
                 : "memory");
}

// --- acc += src; zero the other ping-pong buffer for the next layer --------
__global__ void lg_accum_zero(float4* __restrict__ acc,
                              const float4* __restrict__ src,
                              float4* __restrict__ tozero,
                              int n4) {
    int i = blockIdx.x * blockDim.x + threadIdx.x;
    if (i >= n4) return;
    float4 a = acc[i];
    float4 s = src[i];
    a.x += s.x; a.y += s.y; a.z += s.z; a.w += s.w;
    acc[i] = a;
    tozero[i] = make_float4(0.f, 0.f, 0.f, 0.f);
}

// --- final: out = (acc + last_layer) * 0.25 --------------------------------
__global__ void lg_final(float4* __restrict__ acc,
                         const float4* __restrict__ src,
                         int n4) {
    int i = blockIdx.x * blockDim.x + threadIdx.x;
    if (i >= n4) return;
    float4 a = acc[i];
    float4 s = src[i];
    a.x = (a.x + s.x) * 0.25f;
    a.y = (a.y + s.y) * 0.25f;
    a.z = (a.z + s.z) * 0.25f;
    a.w = (a.w + s.w) * 0.25f;
    acc[i] = a;
}

extern "C" void kernel_launch(void* const* d_in, const int* in_sizes, int n_in,
                              void* d_out, int out_size) {
    const float* user = (const float*)d_in[0];
    const float* item = (const float*)d_in[1];
    const float* vals = (const float*)d_in[2];
    const int*   rows = (const int*)d_in[3];
    const int*   cols = (const int*)d_in[4];

    int n_user  = in_sizes[0] / DIM;
    int n_item  = in_sizes[1] / DIM;
    int nnz     = in_sizes[2];
    int n_total = n_user + n_item;
    int n4      = n_total * DIM4;       // float4 count over the full table
    int n_user4 = n_user * DIM4;

    float* acc = (float*)d_out;

    // device-symbol addresses are compile-time; take them via unqualified ref
    float* bufA; float* bufB;
    cudaGetSymbolAddress((void**)&bufA, g_bufA);
    cudaGetSymbolAddress((void**)&bufB, g_bufB);

    int ew_blocks = (n4 + TPB - 1) / TPB;
    long long spmm_threads = (long long)nnz * DIM4;
    int spmm_blocks = (int)((spmm_threads + TPB - 1) / TPB);

    // init: bufA = concat, acc = concat, bufB = 0
    lg_init<<<ew_blocks, TPB>>>((const float4*)user, (const float4*)item,
                                (float4*)acc, n_user4, n4);

    // layer 1: A -> B ; acc += B ; zero A
    lg_spmm<<<spmm_blocks, TPB>>>(bufA, bufB, vals, rows, cols, nnz);
    lg_accum_zero<<<ew_blocks, TPB>>>((float4*)acc, (const float4*)bufB,
                                      (float4*)bufA, n4);

    // layer 2: B -> A ; acc += A ; zero B
    lg_spmm<<<spmm_blocks, TPB>>>(bufB, bufA, vals, rows, cols, nnz);
    lg_accum_zero<<<ew_blocks, TPB>>>((float4*)acc, (const float4*)bufA,
                                      (float4*)bufB, n4);

    // layer 3: A -> B ; out = (acc + B) / 4
    lg_spmm<<<spmm_blocks, TPB>>>(bufA, bufB, vals, rows, cols, nnz);
    lg_final<<<ew_blocks, TPB>>>((float4*)acc, (const float4*)bufB, n4);
}

// round 3
// speedup vs baseline: 1.7832x; 1.7832x over previous
#include <cuda_runtime.h>

// LightGCN propagation, gather-formulation (no atomics in the hot path):
//   e0 = concat(user_emb, item_emb)            (N = 300000, D = 64)
//   e_{l+1}[r] = sum_{edges e: rows[e]==r} vals[e] * e_l[cols[e]]
//   out = (e0 + e1 + e2 + e3) / 4
//
// Per launch: bucket edges into a padded CSR (one atomic-cursor pass), then
// 3 gather-only SpMM layers (one warp per row, register accumulation, single
// store per row — no pre-zeroing, no RMW atomics), then one fused final pass.

#define DIM      64
#define DIM4     16
#define PAD_W    64              // padded CSR width (deg ~ Poisson(13.3))
#define NMAX     300000
#define OVF_CAP  4096
#define TPB      256

// ---- static scratch (alloc-free rule) -------------------------------------
__device__ int   g_cnt[NMAX];                       // per-row degree / cursor
__device__ uint2 g_list[(size_t)NMAX * PAD_W];      // {col, val_bits}  153.6MB
__device__ int   g_ovf_cnt;
__device__ int4  g_ovf[OVF_CAP];                    // {row, col, val_bits, 0}
__device__ float g_bufB[(size_t)NMAX * DIM];        // layer-1 output
__device__ float g_bufC[(size_t)NMAX * DIM];        // layer-2 output

// ---- zero counters --------------------------------------------------------
__global__ void lg_zero(int n_rows) {
    int i = blockIdx.x * blockDim.x + threadIdx.x;
    if (i < n_rows) g_cnt[i] = 0;
    if (i == 0) g_ovf_cnt = 0;
}

// ---- bucket edges into padded CSR -----------------------------------------
__global__ void lg_build(const int* __restrict__ rows,
                         const int* __restrict__ cols,
                         const float* __restrict__ vals, int nnz) {
    int e = blockIdx.x * blockDim.x + threadIdx.x;
    if (e >= nnz) return;
    int   r = rows[e];
    int   c = cols[e];
    float v = vals[e];
    int pos = atomicAdd(&g_cnt[r], 1);
    if (pos < PAD_W) {
        g_list[(size_t)r * PAD_W + pos] = make_uint2((unsigned)c, __float_as_uint(v));
    } else {
        int o = atomicAdd(&g_ovf_cnt, 1);
        if (o < OVF_CAP) g_ovf[o] = make_int4(r, c, __float_as_int(v), 0);
    }
}

// ---- gather SpMM: one warp per row, lane owns 2 floats of the 64-dim row --
// in = (col < n0) ? in0[col] : in1[col - n0]   (lets layer 1 read raw inputs)
__global__ void lg_gather(const float* __restrict__ in0,
                          const float* __restrict__ in1, int n0,
                          float* __restrict__ out, int n_rows) {
    int warp = (int)((blockIdx.x * (unsigned)blockDim.x + threadIdx.x) >> 5);
    int lane = threadIdx.x & 31;
    if (warp >= n_rows) return;

    int deg = g_cnt[warp];
    if (deg > PAD_W) deg = PAD_W;

    float2 acc = make_float2(0.f, 0.f);
    const size_t base = (size_t)warp * PAD_W;

    for (int start = 0; start < deg; start += 32) {
        int nb = min(32, deg - start);
        uint2 ent = (lane < nb) ? g_list[base + start + lane] : make_uint2(0u, 0u);
        #pragma unroll 4
        for (int j = 0; j < nb; j++) {
            int   c = __shfl_sync(0xffffffff, (int)ent.x, j);
            float v = __uint_as_float(__shfl_sync(0xffffffff, ent.y, j));
            const float* src = (c < n0) ? in0 + (size_t)c * DIM
                                        : in1 + (size_t)(c - n0) * DIM;
            float2 x = *reinterpret_cast<const float2*>(src + 2 * lane);
            acc.x += v * x.x;
            acc.y += v * x.y;
        }
    }
    *reinterpret_cast<float2*>(out + (size_t)warp * DIM + 2 * lane) = acc;
}

// ---- overflow fixup: atomic-add the (expected zero) spilled edges ---------
__global__ void lg_ovf_fix(const float* __restrict__ in0,
                           const float* __restrict__ in1, int n0,
                           float* __restrict__ out) {
    int t = blockIdx.x * blockDim.x + threadIdx.x;
    int e = t >> 4, part = t & 15;
    int n = g_ovf_cnt; if (n > OVF_CAP) n = OVF_CAP;
    if (e >= n) return;
    int4 rec = g_ovf[e];
    const float* src = (rec.y < n0) ? in0 + (size_t)rec.y * DIM
                                    : in1 + (size_t)(rec.y - n0) * DIM;
    float v = __int_as_float(rec.z);
    float4 x = *reinterpret_cast<const float4*>(src + part * 4);
    float* dst = out + (size_t)rec.x * DIM + part * 4;
    asm volatile("red.global.add.v4.f32 [%0], {%1, %2, %3, %4};"
                 :: "l"(dst), "f"(v * x.x), "f"(v * x.y),
                    "f"(v * x.z), "f"(v * x.w) : "memory");
}

// ---- final: out = (concat(user,item) + B + C + out) * 0.25 ----------------
__global__ void lg_final(const float4* __restrict__ user,
                         const float4* __restrict__ item, int n_user4,
                         const float4* __restrict__ B,
                         const float4* __restrict__ C,
                         float4* __restrict__ out, int n4) {
    int i = blockIdx.x * blockDim.x + threadIdx.x;
    if (i >= n4) return;
    float4 e0 = (i < n_user4) ? user[i] : item[i - n_user4];
    float4 b = B[i], c = C[i], o = out[i];
    out[i] = make_float4((e0.x + b.x + c.x + o.x) * 0.25f,
                         (e0.y + b.y + c.y + o.y) * 0.25f,
                         (e0.z + b.z + c.z + o.z) * 0.25f,
                         (e0.w + b.w + c.w + o.w) * 0.25f);
}

extern "C" void kernel_launch(void* const* d_in, const int* in_sizes, int n_in,
                              void* d_out, int out_size) {
    const float* user = (const float*)d_in[0];
    const float* item = (const float*)d_in[1];
    const float* vals = (const float*)d_in[2];
    const int*   rows = (const int*)d_in[3];
    const int*   cols = (const int*)d_in[4];

    int n_user  = in_sizes[0] / DIM;
    int n_item  = in_sizes[1] / DIM;
    int nnz     = in_sizes[2];
    int n_total = n_user + n_item;
    int n4      = n_total * DIM4;
    int n_user4 = n_user * DIM4;

    float* out = (float*)d_out;

    float* bufB; float* bufC;
    cudaGetSymbolAddress((void**)&bufB, g_bufB);
    cudaGetSymbolAddress((void**)&bufC, g_bufC);

    int zero_blocks   = (n_total + TPB - 1) / TPB;
    int build_blocks  = (nnz + TPB - 1) / TPB;
    int gather_blocks = (n_total * 32 + TPB - 1) / TPB;   // 1 warp per row
    int ew_blocks     = (n4 + TPB - 1) / TPB;
    int ovf_blocks    = (OVF_CAP * DIM4 + TPB - 1) / TPB;

    // build padded CSR
    lg_zero<<<zero_blocks, TPB>>>(n_total);
    lg_build<<<build_blocks, TPB>>>(rows, cols, vals, nnz);

    // layer 1: raw inputs -> B
    lg_gather<<<gather_blocks, TPB>>>(user, item, n_user, bufB, n_total);
    lg_ovf_fix<<<ovf_blocks, TPB>>>(user, item, n_user, bufB);

    // layer 2: B -> C
    lg_gather<<<gather_blocks, TPB>>>(bufB, bufB, n_total, bufC, n_total);
    lg_ovf_fix<<<ovf_blocks, TPB>>>(bufB, bufB, n_total, bufC);

    // layer 3: C -> d_out
    lg_gather<<<gather_blocks, TPB>>>(bufC, bufC, n_total, out, n_total);
    lg_ovf_fix<<<ovf_blocks, TPB>>>(bufC, bufC, n_total, out);

    // out = (e0 + e1 + e2 + e3) / 4
    lg_final<<<ew_blocks, TPB>>>((const float4*)user, (const float4*)item,
                                 n_user4, (const float4*)bufB,
                                 (const float4*)bufC, (float4*)out, n4);
}

// round 4
// speedup vs baseline: 1.7855x; 1.0013x over previous
#include <cuda_runtime.h>

// LightGCN propagation, gather-formulation (no atomics in the hot path):
//   e0 = concat(user_emb, item_emb)            (N = 300000, D = 64)
//   e_{l+1}[r] = sum_{edges e: rows[e]==r} vals[e] * e_l[cols[e]]
//   out = (e0 + e1 + e2 + e3) / 4
//
// Per launch: bucket edges into a padded CSR (one atomic-cursor pass), then
// 3 gather-only SpMM layers (one warp per row, register accumulation, single
// store per row — no pre-zeroing, no RMW atomics), then one fused final pass.

#define DIM      64
#define DIM4     16
#define PAD_W    64              // padded CSR width (deg ~ Poisson(13.3))
#define NMAX     300000
#define OVF_CAP  4096
#define TPB      256

// ---- static scratch (alloc-free rule) -------------------------------------
__device__ int   g_cnt[NMAX];                       // per-row degree / cursor
__device__ uint2 g_list[(size_t)NMAX * PAD_W];      // {col, val_bits}  153.6MB
__device__ int   g_ovf_cnt;
__device__ int4  g_ovf[OVF_CAP];                    // {row, col, val_bits, 0}
__device__ float g_bufB[(size_t)NMAX * DIM];        // layer-1 output
__device__ float g_bufC[(size_t)NMAX * DIM];        // layer-2 output

// ---- zero counters --------------------------------------------------------
__global__ void lg_zero(int n_rows) {
    int i = blockIdx.x * blockDim.x + threadIdx.x;
    if (i < n_rows) g_cnt[i] = 0;
    if (i == 0) g_ovf_cnt = 0;
}

// ---- bucket edges into padded CSR -----------------------------------------
__global__ void lg_build(const int* __restrict__ rows,
                         const int* __restrict__ cols,
                         const float* __restrict__ vals, int nnz) {
    int e = blockIdx.x * blockDim.x + threadIdx.x;
    if (e >= nnz) return;
    int   r = rows[e];
    int   c = cols[e];
    float v = vals[e];
    int pos = atomicAdd(&g_cnt[r], 1);
    if (pos < PAD_W) {
        g_list[(size_t)r * PAD_W + pos] = make_uint2((unsigned)c, __float_as_uint(v));
    } else {
        int o = atomicAdd(&g_ovf_cnt, 1);
        if (o < OVF_CAP) g_ovf[o] = make_int4(r, c, __float_as_int(v), 0);
    }
}

// ---- gather SpMM: one warp per row, lane owns 2 floats of the 64-dim row --
// in = (col < n0) ? in0[col] : in1[col - n0]   (lets layer 1 read raw inputs)
__global__ void lg_gather(const float* __restrict__ in0,
                          const float* __restrict__ in1, int n0,
                          float* __restrict__ out, int n_rows) {
    int warp = (int)((blockIdx.x * (unsigned)blockDim.x + threadIdx.x) >> 5);
    int lane = threadIdx.x & 31;
    if (warp >= n_rows) return;

    int deg = g_cnt[warp];
    if (deg > PAD_W) deg = PAD_W;

    float2 acc = make_float2(0.f, 0.f);
    const size_t base = (size_t)warp * PAD_W;

    for (int start = 0; start < deg; start += 32) {
        int nb = min(32, deg - start);
        uint2 ent = (lane < nb) ? g_list[base + start + lane] : make_uint2(0u, 0u);
        #pragma unroll 4
        for (int j = 0; j < nb; j++) {
            int   c = __shfl_sync(0xffffffff, (int)ent.x, j);
            float v = __uint_as_float(__shfl_sync(0xffffffff, ent.y, j));
            const float* src = (c < n0) ? in0 + (size_t)c * DIM
                                        : in1 + (size_t)(c - n0) * DIM;
            float2 x = *reinterpret_cast<const float2*>(src + 2 * lane);
            acc.x += v * x.x;
            acc.y += v * x.y;
        }
    }
    *reinterpret_cast<float2*>(out + (size_t)warp * DIM + 2 * lane) = acc;
}

// ---- overflow fixup: atomic-add the (expected zero) spilled edges ---------
__global__ void lg_ovf_fix(const float* __restrict__ in0,
                           const float* __restrict__ in1, int n0,
                           float* __restrict__ out) {
    int t = blockIdx.x * blockDim.x + threadIdx.x;
    int e = t >> 4, part = t & 15;
    int n = g_ovf_cnt; if (n > OVF_CAP) n = OVF_CAP;
    if (e >= n) return;
    int4 rec = g_ovf[e];
    const float* src = (rec.y < n0) ? in0 + (size_t)rec.y * DIM
                                    : in1 + (size_t)(rec.y - n0) * DIM;
    float v = __int_as_float(rec.z);
    float4 x = *reinterpret_cast<const float4*>(src + part * 4);
    float* dst = out + (size_t)rec.x * DIM + part * 4;
    asm volatile("red.global.add.v4.f32 [%0], {%1, %2, %3, %4};"
                 :: "l"(dst), "f"(v * x.x), "f"(v * x.y),
                    "f"(v * x.z), "f"(v * x.w) : "memory");
}

// ---- final: out = (concat(user,item) + B + C + out) * 0.25 ----------------
__global__ void lg_final(const float4* __restrict__ user,
                         const float4* __restrict__ item, int n_user4,
                         const float4* __restrict__ B,
                         const float4* __restrict__ C,
                         float4* __restrict__ out, int n4) {
    int i = blockIdx.x * blockDim.x + threadIdx.x;
    if (i >= n4) return;
    float4 e0 = (i < n_user4) ? user[i] : item[i - n_user4];
    float4 b = B[i], c = C[i], o = out[i];
    out[i] = make_float4((e0.x + b.x + c.x + o.x) * 0.25f,
                         (e0.y + b.y + c.y + o.y) * 0.25f,
                         (e0.z + b.z + c.z + o.z) * 0.25f,
                         (e0.w + b.w + c.w + o.w) * 0.25f);
}

extern "C" void kernel_launch(void* const* d_in, const int* in_sizes, int n_in,
                              void* d_out, int out_size) {
    const float* user = (const float*)d_in[0];
    const float* item = (const float*)d_in[1];
    const float* vals = (const float*)d_in[2];
    const int*   rows = (const int*)d_in[3];
    const int*   cols = (const int*)d_in[4];

    int n_user  = in_sizes[0] / DIM;
    int n_item  = in_sizes[1] / DIM;
    int nnz     = in_sizes[2];
    int n_total = n_user + n_item;
    int n4      = n_total * DIM4;
    int n_user4 = n_user * DIM4;

    float* out = (float*)d_out;

    float* bufB; float* bufC;
    cudaGetSymbolAddress((void**)&bufB, g_bufB);
    cudaGetSymbolAddress((void**)&bufC, g_bufC);

    int zero_blocks   = (n_total + TPB - 1) / TPB;
    int build_blocks  = (nnz + TPB - 1) / TPB;
    int gather_blocks = (n_total * 32 + TPB - 1) / TPB;   // 1 warp per row
    int ew_blocks     = (n4 + TPB - 1) / TPB;
    int ovf_blocks    = (OVF_CAP * DIM4 + TPB - 1) / TPB;

    // build padded CSR
    lg_zero<<<zero_blocks, TPB>>>(n_total);
    lg_build<<<build_blocks, TPB>>>(rows, cols, vals, nnz);

    // layer 1: raw inputs -> B
    lg_gather<<<gather_blocks, TPB>>>(user, item, n_user, bufB, n_total);
    lg_ovf_fix<<<ovf_blocks, TPB>>>(user, item, n_user, bufB);

    // layer 2: B -> C
    lg_gather<<<gather_blocks, TPB>>>(bufB, bufB, n_total, bufC, n_total);
    lg_ovf_fix<<<ovf_blocks, TPB>>>(bufB, bufB, n_total, bufC);

    // layer 3: C -> d_out
    lg_gather<<<gather_blocks, TPB>>>(bufC, bufC, n_total, out, n_total);
    lg_ovf_fix<<<ovf_blocks, TPB>>>(bufC, bufC, n_total, out);

    // out = (e0 + e1 + e2 + e3) / 4
    lg_final<<<ew_blocks, TPB>>>((const float4*)user, (const float4*)item,
                                 n_user4, (const float4*)bufB,
                                 (const float4*)bufC, (float4*)out, n4);
}